// round 14
// baseline (speedup 1.0000x reference)
#include <cuda_runtime.h>

#define HID   64
#define BATCH 16
#define SEQ   512
#define VOCAB 32000
#define NTOK  (BATCH * SEQ * 2)     // 16384
#define K1_BLOCKS (NTOK / 8)        // 8 warps/block, warp per token -> 2048
#define K2_BLOCKS 512               // 16 batches x 32 chunks of 32 tokens
#define W1T_STRIDE 65

// Scratch (no device allocs). Static zero-init gives first-launch state;
// K2's last block restores invariants (g_acc=0, g_done=0, g_gen++) so every
// graph replay is self-consistent. g_tag uses generation tags => no zeroing.
__device__ int   g_tag[VOCAB];            // last generation that claimed v
__device__ int   g_gen[1];                // generation counter (bumped per launch)
__device__ int   g_done[1];               // K2 completion counter
__device__ float g_rowvec[VOCAB * HID];   // r_v = sos . E_v, keyed by v (8 MB)
__device__ float g_acc[BATCH * HID];      // per-batch hidden (atomic target)

// ---------------------------------------------------------------- K1: claim + rowvec
// Warp per token. Lane0 claims row v via generation atomicMax (first toucher
// wins; duplicates exit). Winner warp: 32 independent float4 loads (each
// warp-load = 512B contiguous), ONE register float4 accumulator
// (hg = lane&15 fixed, w = (lane>>4) + 2j), shfl_xor(16) merge, 16-lane
// 256B coalesced store into g_rowvec[v*HID].
__global__ __launch_bounds__(256) void rowvec_kernel(
    const int*   __restrict__ s1,
    const int*   __restrict__ s2,
    const float* __restrict__ embed,
    const float* __restrict__ sos)
{
    __shared__ float s_sos[HID];
    __shared__ int   s_tok[8];

    const int tid  = threadIdx.x;
    const int wid  = tid >> 5;
    const int lane = tid & 31;

    if (tid < HID) s_sos[tid] = sos[tid];
    if (tid < 8) {
        const int t = blockIdx.x * 8 + tid;       // 0..16383
        const int b = t >> 10;
        const int l = t & 1023;
        s_tok[tid] = (l < SEQ) ? s1[b * SEQ + l]
                               : s2[b * SEQ + (l - SEQ)];
    }
    __syncthreads();

    const int v = s_tok[wid];
    int claimed = 0;
    if (lane == 0) {
        const int gen = g_gen[0] + 1;             // constant within a launch
        claimed = (atomicMax(&g_tag[v], gen) < gen) ? 1 : 0;
    }
    claimed = __shfl_sync(0xffffffffu, claimed, 0);
    if (!claimed) return;                         // duplicate token

    const int wb = lane >> 4;                     // w parity
    const float4* row = reinterpret_cast<const float4*>(embed)
                        + ((long long)v << 10);

    float4 acc = make_float4(0.f, 0.f, 0.f, 0.f);
    #pragma unroll
    for (int j = 0; j < 32; j++) {
        const float4 x = __ldg(&row[lane + (j << 5)]);
        const float  s = s_sos[wb + (j << 1)];
        acc.x = fmaf(s, x.x, acc.x); acc.y = fmaf(s, x.y, acc.y);
        acc.z = fmaf(s, x.z, acc.z); acc.w = fmaf(s, x.w, acc.w);
    }
    acc.x += __shfl_xor_sync(0xffffffffu, acc.x, 16);
    acc.y += __shfl_xor_sync(0xffffffffu, acc.y, 16);
    acc.z += __shfl_xor_sync(0xffffffffu, acc.z, 16);
    acc.w += __shfl_xor_sync(0xffffffffu, acc.w, 16);

    if (lane < 16)
        reinterpret_cast<float4*>(&g_rowvec[(long long)v * HID])[lane] = acc;
}

// ---------------------------------------------------------------- K2: accum + MLP + cleanup
// 512 blocks = 16 batches x 32 chunks of 32 tokens. Per thread: 2 scattered
// float4 loads (token -> rowvec, only 2 dependent rounds), block-reduce,
// 64 atomicAdds/block into g_acc. Last finishing block (threadfence-
// reduction pattern) runs the full MLP for all 16 batches, writes out,
// zeroes g_acc, resets g_done, bumps g_gen.
__global__ __launch_bounds__(256) void accum_mlp_kernel(
    const int*   __restrict__ s1,
    const int*   __restrict__ s2,
    const float* __restrict__ w1,
    const float* __restrict__ b1,
    const float* __restrict__ w2,
    const float* __restrict__ b2,
    float*       __restrict__ out)
{
    __shared__ int    s_tok[32];
    __shared__ float4 s_red[256];
    __shared__ int    s_last;
    __shared__ float  w1t[HID * W1T_STRIDE];      // used by last block only
    __shared__ float  shh[BATCH * HID];
    __shared__ float  sxx[BATCH * HID];

    const int tid   = threadIdx.x;
    const int b     = blockIdx.x >> 5;
    const int chunk = blockIdx.x & 31;

    if (tid < 32) {
        const int l = chunk * 32 + tid;           // 0..1023
        s_tok[tid] = (l < SEQ) ? s1[b * SEQ + l]
                               : s2[b * SEQ + (l - SEQ)];
    }
    __syncthreads();

    const int hg = tid & 15;
    const int tg = tid >> 4;                      // 0..15
    const float4* rv = reinterpret_cast<const float4*>(g_rowvec);

    const float4 p0 = __ldg(&rv[(long long)s_tok[tg]      * 16 + hg]);
    const float4 p1 = __ldg(&rv[(long long)s_tok[tg + 16] * 16 + hg]);
    float4 a;
    a.x = p0.x + p1.x; a.y = p0.y + p1.y;
    a.z = p0.z + p1.z; a.w = p0.w + p1.w;
    s_red[tid] = a;
    __syncthreads();

    if (tid < 16) {
        float4 sum = make_float4(0.f, 0.f, 0.f, 0.f);
        #pragma unroll
        for (int j = 0; j < 16; j++) {
            const float4 p = s_red[(j << 4) + tid];
            sum.x += p.x; sum.y += p.y; sum.z += p.z; sum.w += p.w;
        }
        float* dst = &g_acc[b * HID + (tid << 2)];
        atomicAdd(dst + 0, sum.x);
        atomicAdd(dst + 1, sum.y);
        atomicAdd(dst + 2, sum.z);
        atomicAdd(dst + 3, sum.w);
    }
    __syncthreads();

    if (tid == 0) {
        __threadfence();                          // publish this block's adds
        s_last = (atomicAdd(&g_done[0], 1) == (int)gridDim.x - 1) ? 1 : 0;
    }
    __syncthreads();
    if (!s_last) return;

    // ---------------- last block: full MLP for all batches ----------------
    __threadfence();                              // acquire all blocks' adds

    // Stage w1 transposed (pad-65) + read accumulated hidden.
    #pragma unroll
    for (int j = 0; j < 16; j++) {
        const int idx = tid + 256 * j;            // 0..4095
        w1t[(idx & 63) * W1T_STRIDE + (idx >> 6)] = w1[idx];
    }
    #pragma unroll
    for (int j = 0; j < 4; j++) {
        const int id = tid + 256 * j;             // 0..1023
        shh[id] = g_acc[id];
    }
    __syncthreads();

    // Layer 1 + ReLU: 1024 outputs, 4 per thread.
    #pragma unroll
    for (int j = 0; j < 4; j++) {
        const int id = tid + 256 * j;
        const int bb = id >> 6;
        const int h  = id & 63;
        float sum = b1[h];
        const float* hb = &shh[bb * HID];
        #pragma unroll
        for (int k = 0; k < HID; k++)
            sum = fmaf(hb[k], w1t[k * W1T_STRIDE + h], sum);
        sxx[id] = fmaxf(sum, 0.0f);
    }
    __syncthreads();

    // Layer 2: 32 outputs.
    if (tid < BATCH * 2) {
        const int bb = tid >> 1;
        const int o  = tid & 1;
        float s = b2[o];
        #pragma unroll
        for (int k = 0; k < HID; k++)
            s = fmaf(sxx[bb * HID + k], w2[o * HID + k], s);
        out[bb * 2 + o] = s;
    }

    // Cleanup for the next replay.
    #pragma unroll
    for (int j = 0; j < 4; j++)
        g_acc[tid + 256 * j] = 0.0f;
    if (tid == 0) {
        g_done[0] = 0;
        g_gen[0] = g_gen[0] + 1;
    }
}

extern "C" void kernel_launch(void* const* d_in, const int* in_sizes, int n_in,
                              void* d_out, int out_size)
{
    const int*   s1    = (const int*)  d_in[0];
    const int*   s2    = (const int*)  d_in[1];
    const float* embed = (const float*)d_in[2];
    const float* sos   = (const float*)d_in[3];
    const float* w1    = (const float*)d_in[4];
    const float* b1    = (const float*)d_in[5];
    const float* w2    = (const float*)d_in[6];
    const float* b2    = (const float*)d_in[7];
    float* out = (float*)d_out;

    rowvec_kernel<<<K1_BLOCKS, 256>>>(s1, s2, embed, sos);
    accum_mlp_kernel<<<K2_BLOCKS, 256>>>(s1, s2, w1, b1, w2, b2, out);
}

// round 15
// speedup vs baseline: 1.1017x; 1.1017x over previous
#include <cuda_runtime.h>

#define HID   64
#define BATCH 16
#define SEQ   512
#define T_PER_BLK 16                      // tokens per gather block
#define NCHUNK (1024 / T_PER_BLK)         // 64 chunks per batch

// Per-batch hidden accumulator. Static zero-init covers the first launch;
// mlp_kernel zeroes its batch slice after reading, so the correctness run
// and every graph replay start from g_acc == 0. Deterministic work; float
// atomic ordering variance ~1e-7 (<< 1e-3 threshold).
__device__ float g_acc[BATCH * HID];

// ---------------------------------------------------------------- gather
// (Proven ~7.1 TB/s config from R6 — structure untouched.)
// Block: 256 threads, 16 tokens. Row = 1024 float4. Thread tid loads float4
// index f = tid + 256*j (j=0..3): w = (tid>>4)+16j, and the float4 always
// lands on h = (tid&15)*4 .. +3 — one float4 accumulator per thread.
// NEW: block result goes straight into g_acc via 64 atomicAdds (REDG,
// 32 ops/address across the launch — hidden under the stream).
__global__ __launch_bounds__(256) void gather_kernel(
    const int*   __restrict__ s1,
    const int*   __restrict__ s2,
    const float* __restrict__ embed,
    const float* __restrict__ sos)
{
    __shared__ float  s_sos[HID];
    __shared__ int    s_tok[T_PER_BLK];
    __shared__ float4 red[256];

    const int b   = blockIdx.x;           // batch
    const int c   = blockIdx.y;           // token chunk 0..63
    const int tid = threadIdx.x;

    if (tid < HID) s_sos[tid] = sos[tid];
    if (tid < T_PER_BLK) {
        const int l = c * T_PER_BLK + tid;        // 0..1023
        s_tok[tid] = (l < SEQ) ? s1[b * SEQ + l]
                               : s2[b * SEQ + (l - SEQ)];
    }
    __syncthreads();

    const int   wbase = tid >> 4;         // 0..15
    const float s0 = s_sos[wbase];
    const float sA = s_sos[wbase + 16];
    const float sB = s_sos[wbase + 32];
    const float sC = s_sos[wbase + 48];

    float4 acc = make_float4(0.f, 0.f, 0.f, 0.f);

    #pragma unroll 4
    for (int i = 0; i < T_PER_BLK; i++) {
        const float4* row = reinterpret_cast<const float4*>(embed)
                            + ((long long)s_tok[i] << 10);
        const float4 v0 = __ldg(&row[tid      ]);
        const float4 v1 = __ldg(&row[tid + 256]);
        const float4 v2 = __ldg(&row[tid + 512]);
        const float4 v3 = __ldg(&row[tid + 768]);
        acc.x = fmaf(s0, v0.x, acc.x); acc.y = fmaf(s0, v0.y, acc.y);
        acc.z = fmaf(s0, v0.z, acc.z); acc.w = fmaf(s0, v0.w, acc.w);
        acc.x = fmaf(sA, v1.x, acc.x); acc.y = fmaf(sA, v1.y, acc.y);
        acc.z = fmaf(sA, v1.z, acc.z); acc.w = fmaf(sA, v1.w, acc.w);
        acc.x = fmaf(sB, v2.x, acc.x); acc.y = fmaf(sB, v2.y, acc.y);
        acc.z = fmaf(sB, v2.z, acc.z); acc.w = fmaf(sB, v2.w, acc.w);
        acc.x = fmaf(sC, v3.x, acc.x); acc.y = fmaf(sC, v3.y, acc.y);
        acc.z = fmaf(sC, v3.z, acc.z); acc.w = fmaf(sC, v3.w, acc.w);
    }

    red[tid] = acc;
    __syncthreads();

    // 16 threads: h-group tid sums its 16 w-partials, then 4 atomicAdds.
    if (tid < 16) {
        float4 sum = make_float4(0.f, 0.f, 0.f, 0.f);
        #pragma unroll
        for (int j = 0; j < 16; j++) {
            const float4 v = red[tid + (j << 4)];
            sum.x += v.x; sum.y += v.y; sum.z += v.z; sum.w += v.w;
        }
        float* dst = &g_acc[b * HID + (tid << 2)];
        atomicAdd(dst + 0, sum.x);
        atomicAdd(dst + 1, sum.y);
        atomicAdd(dst + 2, sum.z);
        atomicAdd(dst + 3, sum.w);
    }
}

// ---------------------------------------------------------------- MLP
// One block per batch, 256 threads. Reads just 64 floats of g_acc + 16 KB
// w1 (staged transposed, pad-65 -> conflict-free), computes both layers,
// writes 2 outputs, then ZEROES its g_acc slice for the next replay.
#define W1T_STRIDE 65
__global__ __launch_bounds__(256) void mlp_kernel(
    const float* __restrict__ w1,
    const float* __restrict__ b1,
    const float* __restrict__ w2,
    const float* __restrict__ b2,
    float*       __restrict__ out)
{
    __shared__ float w1t[HID * W1T_STRIDE];   // 16.6 KB
    __shared__ float sh[HID];
    __shared__ float sx[HID];

    const int b   = blockIdx.x;
    const int tid = threadIdx.x;

    // Stage w1 transposed (coalesced read, conflict-free write).
    #pragma unroll
    for (int j = 0; j < 16; j++) {
        const int idx = tid + 256 * j;            // 0..4095
        w1t[(idx & 63) * W1T_STRIDE + (idx >> 6)] = w1[idx];
    }
    if (tid < HID) sh[tid] = g_acc[b * HID + tid];
    __syncthreads();

    // Layer 1 + ReLU (threads 0..63; sh broadcast; w1t conflict-free).
    if (tid < HID) {
        float sum = b1[tid];
        #pragma unroll
        for (int k = 0; k < HID; k++)
            sum = fmaf(sh[k], w1t[k * W1T_STRIDE + tid], sum);
        sx[tid] = fmaxf(sum, 0.0f);

        // Restore invariant for the next graph replay.
        g_acc[b * HID + tid] = 0.0f;
    }
    __syncthreads();

    // Layer 2: 2 outputs for this batch.
    if (tid < 2) {
        float s2 = b2[tid];
        #pragma unroll
        for (int k = 0; k < HID; k++)
            s2 = fmaf(sx[k], w2[tid * HID + k], s2);
        out[b * 2 + tid] = s2;
    }
}

extern "C" void kernel_launch(void* const* d_in, const int* in_sizes, int n_in,
                              void* d_out, int out_size)
{
    const int*   s1    = (const int*)  d_in[0];
    const int*   s2    = (const int*)  d_in[1];
    const float* embed = (const float*)d_in[2];
    const float* sos   = (const float*)d_in[3];
    const float* w1    = (const float*)d_in[4];
    const float* b1    = (const float*)d_in[5];
    const float* w2    = (const float*)d_in[6];
    const float* b2    = (const float*)d_in[7];
    float* out = (float*)d_out;

    dim3 grid(BATCH, NCHUNK);
    gather_kernel<<<grid, 256>>>(s1, s2, embed, sos);
    mlp_kernel<<<BATCH, 256>>>(w1, b1, w2, b2, out);
}